// round 17
// baseline (speedup 1.0000x reference)
#include <cuda_runtime.h>
#include <cuda_bf16.h>
#include <cuda_fp16.h>
#include <cstdint>
#include <math.h>

#define BB 2
#define SS 2048
#define HH 1024
#define NHH 16
#define HDD 64
#define MM (BB*SS)          // 4096
#define HSQ (HH*HH)

// ---------------------------------------------------------------------------
// Scratch
// ---------------------------------------------------------------------------
__device__ __half g_Qh[MM * HH];    // [B,NH,S,HD] fp16, Q pre-scaled by 0.125*log2e
__device__ __half g_Kh[MM * HH];
__device__ __half g_Vh[MM * HH];
__device__ __half g_Xh[MM * HH];
__device__ __half g_WTh[3 * HSQ];
__device__ __half g_Ch[MM * HH];
__device__ __half g_WOh[HSQ];
__device__ __half g_mh[BB * SS];    // mask as fp16: 0 (keep) / -inf (drop)

// ---------------------------------------------------------------------------
// Helpers
// ---------------------------------------------------------------------------
__device__ __forceinline__ uint32_t smem_u32(const void* p) {
    uint32_t a;
    asm("{ .reg .u64 t; cvta.to.shared.u64 t, %1; cvt.u32.u64 %0, t; }" : "=r"(a) : "l"(p));
    return a;
}
__device__ __forceinline__ void ldm_x4(uint32_t& r0, uint32_t& r1, uint32_t& r2,
                                       uint32_t& r3, uint32_t addr) {
    asm volatile("ldmatrix.sync.aligned.m8n8.x4.shared.b16 {%0,%1,%2,%3}, [%4];"
                 : "=r"(r0), "=r"(r1), "=r"(r2), "=r"(r3) : "r"(addr));
}
__device__ __forceinline__ void ldm_x4_t(uint32_t& r0, uint32_t& r1, uint32_t& r2,
                                         uint32_t& r3, uint32_t addr) {
    asm volatile("ldmatrix.sync.aligned.m8n8.x4.trans.shared.b16 {%0,%1,%2,%3}, [%4];"
                 : "=r"(r0), "=r"(r1), "=r"(r2), "=r"(r3) : "r"(addr));
}
__device__ __forceinline__ void ldm_x2(uint32_t& r0, uint32_t& r1, uint32_t addr) {
    asm volatile("ldmatrix.sync.aligned.m8n8.x2.shared.b16 {%0,%1}, [%2];"
                 : "=r"(r0), "=r"(r1) : "r"(addr));
}
__device__ __forceinline__ void mma_f16(float* c, const uint32_t* a, uint32_t b0, uint32_t b1) {
    asm volatile(
        "mma.sync.aligned.m16n8k16.row.col.f32.f16.f16.f32 "
        "{%0,%1,%2,%3}, {%4,%5,%6,%7}, {%8,%9}, {%0,%1,%2,%3};"
        : "+f"(c[0]), "+f"(c[1]), "+f"(c[2]), "+f"(c[3])
        : "r"(a[0]), "r"(a[1]), "r"(a[2]), "r"(a[3]), "r"(b0), "r"(b1));
}
// f16-accumulator MMA (equal rate to f32-acc on sm_103a; saves the cvts)
__device__ __forceinline__ void mma_f16a(uint32_t* c, const uint32_t* a,
                                         uint32_t b0, uint32_t b1) {
    asm volatile(
        "mma.sync.aligned.m16n8k16.row.col.f16.f16.f16.f16 "
        "{%0,%1}, {%2,%3,%4,%5}, {%6,%7}, {%0,%1};"
        : "+r"(c[0]), "+r"(c[1])
        : "r"(a[0]), "r"(a[1]), "r"(a[2]), "r"(a[3]), "r"(b0), "r"(b1));
}
__device__ __forceinline__ __half2 h2exp2f(__half2 x) {
    __half2 y;
    asm("ex2.approx.f16x2 %0, %1;"
        : "=r"(*(uint32_t*)&y) : "r"(*(uint32_t*)&x));
    return y;
}
#define CP_ASYNC16(dst_u32, src_gptr) \
    asm volatile("cp.async.cg.shared.global [%0], [%1], 16;" \
                 :: "r"(dst_u32), "l"(src_gptr) : "memory")
#define CP_COMMIT() asm volatile("cp.async.commit_group;" ::: "memory")
#define CP_WAIT1()  asm volatile("cp.async.wait_group 1;" ::: "memory")
#define CP_WAIT0()  asm volatile("cp.async.wait_group 0;" ::: "memory")

// ---------------------------------------------------------------------------
// Merged conversion kernel (unchanged)
// ---------------------------------------------------------------------------
__global__ __launch_bounds__(256) void conv_all(
    const float* __restrict__ X, const int* __restrict__ mask,
    const float* __restrict__ Wq, const float* __restrict__ Wk,
    const float* __restrict__ Wv, const float* __restrict__ Wo)
{
    const int z = blockIdx.z;
    if (z < 4) {
        __shared__ float t[32][33];
        const float* W = (z == 0) ? Wq : (z == 1) ? Wk : (z == 2) ? Wv : Wo;
        int n0 = blockIdx.x * 32, k0 = blockIdx.y * 32;
        for (int i = threadIdx.y; i < 32; i += 8)
            t[i][threadIdx.x] = W[(size_t)(k0 + i) * HH + n0 + threadIdx.x];
        __syncthreads();
        __half* dst = (z < 3) ? (g_WTh + (size_t)z * HSQ) : g_WOh;
        for (int i = threadIdx.y; i < 32; i += 8)
            dst[(size_t)(n0 + i) * HH + k0 + threadIdx.x] = __float2half(t[threadIdx.x][i]);
    } else {
        const int tid = threadIdx.y * 32 + threadIdx.x;
        const int blk = blockIdx.y * 32 + blockIdx.x;
        int i0 = blk * 1024 + tid;
        __half2* dst = (__half2*)g_Xh;
#pragma unroll
        for (int k = 0; k < 4; k++) {
            int i = i0 + k * 256;
            float4 v = ((const float4*)X)[i];
            dst[2 * i]     = __floats2half2_rn(v.x, v.y);
            dst[2 * i + 1] = __floats2half2_rn(v.z, v.w);
        }
        if (blockIdx.y == 0 && tid < 128) {
            int i = blockIdx.x * 128 + tid;
            g_mh[i] = mask[i] ? __ushort_as_half(0x0000) : __ushort_as_half(0xFC00);
        }
    }
}

// ---------------------------------------------------------------------------
// QKV GEMM with software-pipelined fragments: ks+1's LDSMs issue before
// ks's MMA wall (double-buffered af/bf registers).
// ---------------------------------------------------------------------------
#define QSTAGE 32768
#define QSMEM  (3 * QSTAGE)   // 96KB

__global__ __launch_bounds__(256, 2) void gemm_qkv_f16()
{
    extern __shared__ char gsm[];
    const uint32_t sb = smem_u32(gsm);
    const int tid = threadIdx.x;
    const int lane = tid & 31;
    const int wid = tid >> 5;
    const int wm = wid >> 2;
    const int wn = wid & 3;

    const __half* A = g_Xh;
    const __half* Bw = g_WTh + (size_t)blockIdx.z * HSQ;
    const int mRow0 = blockIdx.y * 128;
    const int nCol0 = blockIdx.x * 128;

    // precomputed per-thread fragment row offsets
    const int a_row = wm * 64 + (lane & 15);
    const int b_row = wn * 32 + (lane & 7);
    const int a_cbase = lane >> 4;           // 0/1
    const int b_cbase = (lane >> 3) & 1;     // 0/1

    float acc[4][4][4];
#pragma unroll
    for (int i = 0; i < 4; i++)
#pragma unroll
        for (int j = 0; j < 4; j++)
#pragma unroll
            for (int k = 0; k < 4; k++) acc[i][j][k] = 0.f;

    auto load_stage = [&](int st, int kk) {
        uint32_t base = sb + st * QSTAGE;
#pragma unroll
        for (int u = tid; u < 2048; u += 256) {
            int region = u >> 10;
            int idx = u & 1023;
            int r = idx >> 3;
            int c = idx & 7;
            const __half* src = (region ? Bw + (size_t)(nCol0 + r) * HH
                                        : A + (size_t)(mRow0 + r) * HH) + kk + c * 8;
            uint32_t dst = base + region * 16384 + r * 128 + ((c ^ (r & 7)) << 4);
            CP_ASYNC16(dst, src);
        }
    };
    auto load_frags = [&](uint32_t base, int ks, uint32_t af[4][4], uint32_t bf[4][2]) {
#pragma unroll
        for (int mt = 0; mt < 4; mt++) {
            int row = a_row + mt * 16;
            int c = ks * 2 + a_cbase;
            ldm_x4(af[mt][0], af[mt][1], af[mt][2], af[mt][3],
                   base + row * 128 + ((c ^ (row & 7)) << 4));
        }
#pragma unroll
        for (int nt = 0; nt < 4; nt++) {
            int row = b_row + nt * 8;
            int c = ks * 2 + b_cbase;
            ldm_x2(bf[nt][0], bf[nt][1],
                   base + 16384 + row * 128 + ((c ^ (row & 7)) << 4));
        }
    };

    load_stage(0, 0);
    CP_COMMIT();
    load_stage(1, 64);
    CP_COMMIT();

#pragma unroll 1
    for (int ch = 0; ch < 16; ch++) {
        if (ch < 14) CP_WAIT1(); else CP_WAIT0();
        __syncthreads();
        if (ch + 2 < 16) {
            load_stage((ch + 2) % 3, (ch + 2) * 64);
            CP_COMMIT();
        }

        const uint32_t base = sb + (ch % 3) * QSTAGE;
        uint32_t af[2][4][4], bf[2][4][2];
        load_frags(base, 0, af[0], bf[0]);
#pragma unroll
        for (int ks = 0; ks < 4; ks++) {
            const int cur = ks & 1;
            if (ks < 3)
                load_frags(base, ks + 1, af[cur ^ 1], bf[cur ^ 1]);
#pragma unroll
            for (int mt = 0; mt < 4; mt++)
#pragma unroll
                for (int nt = 0; nt < 4; nt++)
                    mma_f16(acc[mt][nt], af[cur][mt], bf[cur][nt][0], bf[cur][nt][1]);
        }
    }

    __half* outp = (blockIdx.z == 0) ? g_Qh : (blockIdx.z == 1) ? g_Kh : g_Vh;
    const float scale = (blockIdx.z == 0) ? 0.125f * 1.4426950408889634f : 1.0f;
#pragma unroll
    for (int mt = 0; mt < 4; mt++)
#pragma unroll
        for (int nt = 0; nt < 4; nt++) {
            int m = mRow0 + wm * 64 + mt * 16 + (lane >> 2);
            int n = nCol0 + wn * 32 + nt * 8 + 2 * (lane & 3);
            int b = m >> 11, s = m & 2047, h = n >> 6, d = n & 63;
            size_t i0 = ((size_t)(b * NHH + h) * SS + s) * HDD + d;
            size_t i1 = ((size_t)(b * NHH + h) * SS + (s + 8)) * HDD + d;
            *(__half2*)&outp[i0] = __floats2half2_rn(acc[mt][nt][0] * scale,
                                                     acc[mt][nt][1] * scale);
            *(__half2*)&outp[i1] = __floats2half2_rn(acc[mt][nt][2] * scale,
                                                     acc[mt][nt][3] * scale);
        }
}

// ---------------------------------------------------------------------------
// O-proj GEMM, same software-pipelined engine.
// ---------------------------------------------------------------------------
__global__ __launch_bounds__(256, 2) void gemm_out_f16(float* __restrict__ out)
{
    extern __shared__ char gsm[];
    const uint32_t sb = smem_u32(gsm);
    const int tid = threadIdx.x;
    const int lane = tid & 31;
    const int wid = tid >> 5;
    const int wm = wid >> 2;
    const int wn = wid & 3;

    const __half* A = g_Ch;
    const __half* Bw = g_WOh;
    const int mRow0 = blockIdx.y * 128;
    const int nCol0 = blockIdx.x * 128;

    const int a_row = wm * 64 + (lane & 15);
    const int b_row = wn * 32 + (lane & 7);
    const int a_cbase = lane >> 4;
    const int b_cbase = (lane >> 3) & 1;

    float acc[4][4][4];
#pragma unroll
    for (int i = 0; i < 4; i++)
#pragma unroll
        for (int j = 0; j < 4; j++)
#pragma unroll
            for (int k = 0; k < 4; k++) acc[i][j][k] = 0.f;

    auto load_stage = [&](int st, int kk) {
        uint32_t base = sb + st * QSTAGE;
#pragma unroll
        for (int u = tid; u < 2048; u += 256) {
            int region = u >> 10;
            int idx = u & 1023;
            int r = idx >> 3;
            int c = idx & 7;
            const __half* src = (region ? Bw + (size_t)(nCol0 + r) * HH
                                        : A + (size_t)(mRow0 + r) * HH) + kk + c * 8;
            uint32_t dst = base + region * 16384 + r * 128 + ((c ^ (r & 7)) << 4);
            CP_ASYNC16(dst, src);
        }
    };
    auto load_frags = [&](uint32_t base, int ks, uint32_t af[4][4], uint32_t bf[4][2]) {
#pragma unroll
        for (int mt = 0; mt < 4; mt++) {
            int row = a_row + mt * 16;
            int c = ks * 2 + a_cbase;
            ldm_x4(af[mt][0], af[mt][1], af[mt][2], af[mt][3],
                   base + row * 128 + ((c ^ (row & 7)) << 4));
        }
#pragma unroll
        for (int nt = 0; nt < 4; nt++) {
            int row = b_row + nt * 8;
            int c = ks * 2 + b_cbase;
            ldm_x2(bf[nt][0], bf[nt][1],
                   base + 16384 + row * 128 + ((c ^ (row & 7)) << 4));
        }
    };

    load_stage(0, 0);
    CP_COMMIT();
    load_stage(1, 64);
    CP_COMMIT();

#pragma unroll 1
    for (int ch = 0; ch < 16; ch++) {
        if (ch < 14) CP_WAIT1(); else CP_WAIT0();
        __syncthreads();
        if (ch + 2 < 16) {
            load_stage((ch + 2) % 3, (ch + 2) * 64);
            CP_COMMIT();
        }

        const uint32_t base = sb + (ch % 3) * QSTAGE;
        uint32_t af[2][4][4], bf[2][4][2];
        load_frags(base, 0, af[0], bf[0]);
#pragma unroll
        for (int ks = 0; ks < 4; ks++) {
            const int cur = ks & 1;
            if (ks < 3)
                load_frags(base, ks + 1, af[cur ^ 1], bf[cur ^ 1]);
#pragma unroll
            for (int mt = 0; mt < 4; mt++)
#pragma unroll
                for (int nt = 0; nt < 4; nt++)
                    mma_f16(acc[mt][nt], af[cur][mt], bf[cur][nt][0], bf[cur][nt][1]);
        }
    }

#pragma unroll
    for (int mt = 0; mt < 4; mt++)
#pragma unroll
        for (int nt = 0; nt < 4; nt++) {
            int m = mRow0 + wm * 64 + mt * 16 + (lane >> 2);
            int n = nCol0 + wn * 32 + nt * 8 + 2 * (lane & 3);
            *(float2*)&out[(size_t)m * HH + n] =
                make_float2(acc[mt][nt][0], acc[mt][nt][1]);
            *(float2*)&out[(size_t)(m + 8) * HH + n] =
                make_float2(acc[mt][nt][2], acc[mt][nt][3]);
        }
}

// ---------------------------------------------------------------------------
// Flash attention (R16 form, unchanged — f16-acc QK, fixed-base softmax)
// ---------------------------------------------------------------------------
#define AQS 0
#define AKV(s) (8192 + (s) * 16384)
#define AMH(s) (40960 + (s) * 128)
#define ASMEM  41216
#define HONES  0x3C003C00u

__global__ __launch_bounds__(128, 4) void attn_mma()
{
    extern __shared__ char smraw[];
    const uint32_t sb = smem_u32(smraw);

    const int t = threadIdx.x;
    const int w = t >> 5;
    const int lane = t & 31;
    const int bh = blockIdx.y;
    const int b = bh >> 4;
    const int h = bh & 15;
    const int q0 = blockIdx.x * 64;

    const __half* Qg = g_Qh + ((size_t)bh * SS + q0) * HDD;
    const __half* Kg = g_Kh + (size_t)bh * SS * HDD;
    const __half* Vg = g_Vh + (size_t)bh * SS * HDD;
    const __half* mg = g_mh + b * SS;

    auto load_kv = [&](int st, int kt) {
        uint32_t kb = sb + AKV(st);
#pragma unroll
        for (int u = t; u < 1024; u += 128) {
            int region = u >> 9;
            int idx = u & 511;
            int r = idx >> 3, c = idx & 7;
            const __half* src = (region ? Vg : Kg) + (size_t)(kt + r) * HDD + c * 8;
            CP_ASYNC16(kb + region * 8192 + r * 128 + ((c ^ (r & 7)) << 4), src);
        }
        if (t < 8)
            CP_ASYNC16(sb + AMH(st) + t * 16, mg + kt + t * 8);
    };

    for (int u = t; u < 512; u += 128) {
        int r = u >> 3, c = u & 7;
        CP_ASYNC16(sb + AQS + r * 128 + ((c ^ (r & 7)) << 4),
                   Qg + (size_t)r * HDD + c * 8);
    }
    load_kv(0, 0);
    CP_COMMIT();
    CP_WAIT0();
    __syncthreads();

    uint32_t qa[4][4];
#pragma unroll
    for (int ks = 0; ks < 4; ks++) {
        int row = w * 16 + (lane & 15);
        int c = ks * 2 + (lane >> 4);
        ldm_x4(qa[ks][0], qa[ks][1], qa[ks][2], qa[ks][3],
               sb + AQS + row * 128 + ((c ^ (row & 7)) << 4));
    }

    float lacc[4] = {0.f, 0.f, 0.f, 0.f};
    float o[8][4];
#pragma unroll
    for (int dd = 0; dd < 8; dd++)
#pragma unroll
        for (int k = 0; k < 4; k++) o[dd][k] = 0.f;

#pragma unroll 1
    for (int it = 0; it < 32; it++) {
        const int cur = it & 1;
        if (it + 1 < 32) {
            load_kv(cur ^ 1, (it + 1) * 64);
            CP_COMMIT();
        }

        const uint32_t kb = sb + AKV(cur);

        uint32_t sc[8][2];
#pragma unroll
        for (int nt = 0; nt < 8; nt++) { sc[nt][0] = 0u; sc[nt][1] = 0u; }
#pragma unroll
        for (int ntp = 0; ntp < 4; ntp++) {
#pragma unroll
            for (int ks = 0; ks < 4; ks++) {
                int row = ntp * 16 + ((lane >> 4) << 3) + (lane & 7);
                int c = ks * 2 + ((lane >> 3) & 1);
                uint32_t r0, r1, r2, r3;
                ldm_x4(r0, r1, r2, r3, kb + row * 128 + ((c ^ (row & 7)) << 4));
                mma_f16a(sc[2 * ntp], qa[ks], r0, r1);
                mma_f16a(sc[2 * ntp + 1], qa[ks], r2, r3);
            }
        }

        const __half2* mh2 = (const __half2*)(smraw + AMH(cur));
        const int ci = lane & 3;
        __half2 hp0[8], hp1[8];
#pragma unroll
        for (int nt = 0; nt < 8; nt++) {
            __half2 m2 = mh2[nt * 4 + ci];
            hp0[nt] = h2exp2f(__hadd2(*(__half2*)&sc[nt][0], m2));
            hp1[nt] = h2exp2f(__hadd2(*(__half2*)&sc[nt][1], m2));
        }

        const uint32_t vb = kb + 8192;
#pragma unroll
        for (int jj = 0; jj < 4; jj++) {
            uint32_t pa[4];
            pa[0] = *(uint32_t*)&hp0[2 * jj];
            pa[1] = *(uint32_t*)&hp1[2 * jj];
            pa[2] = *(uint32_t*)&hp0[2 * jj + 1];
            pa[3] = *(uint32_t*)&hp1[2 * jj + 1];
            mma_f16(lacc, pa, HONES, HONES);
#pragma unroll
            for (int ddp = 0; ddp < 4; ddp++) {
                int row = jj * 16 + ((lane >> 3) & 1) * 8 + (lane & 7);
                int ch = ddp * 2 + (lane >> 4);
                uint32_t r0, r1, r2, r3;
                ldm_x4_t(r0, r1, r2, r3, vb + row * 128 + ((ch ^ (row & 7)) << 4));
                mma_f16(o[2 * ddp], pa, r0, r1);
                mma_f16(o[2 * ddp + 1], pa, r2, r3);
            }
        }

        if (it + 1 < 32) {
            CP_WAIT0();
            __syncthreads();
        }
    }

    float inv0 = 1.f / lacc[0], inv1 = 1.f / lacc[2];
    int r0g = q0 + w * 16 + (lane >> 2);
    size_t base0 = ((size_t)(b * SS + r0g)) * HH + h * 64;
    size_t base1 = base0 + (size_t)8 * HH;
#pragma unroll
    for (int dd = 0; dd < 8; dd++) {
        int d = dd * 8 + 2 * (lane & 3);
        *(__half2*)&g_Ch[base0 + d] = __floats2half2_rn(o[dd][0] * inv0, o[dd][1] * inv0);
        *(__half2*)&g_Ch[base1 + d] = __floats2half2_rn(o[dd][2] * inv1, o[dd][3] * inv1);
    }
}

// ---------------------------------------------------------------------------
// Launch
// ---------------------------------------------------------------------------
extern "C" void kernel_launch(void* const* d_in, const int* in_sizes, int n_in,
                              void* d_out, int out_size)
{
    const float* X    = (const float*)d_in[0];
    const int*   mask = (const int*)  d_in[1];
    const float* Wq   = (const float*)d_in[2];
    const float* Wk   = (const float*)d_in[3];
    const float* Wv   = (const float*)d_in[4];
    const float* Wo   = (const float*)d_in[5];
    float* out = (float*)d_out;

    conv_all<<<dim3(32, 32, 5), dim3(32, 8)>>>(X, mask, Wq, Wk, Wv, Wo);

    cudaFuncSetAttribute(gemm_qkv_f16, cudaFuncAttributeMaxDynamicSharedMemorySize, QSMEM);
    gemm_qkv_f16<<<dim3(HH / 128, MM / 128, 3), 256, QSMEM>>>();

    cudaFuncSetAttribute(attn_mma, cudaFuncAttributeMaxDynamicSharedMemorySize, ASMEM);
    attn_mma<<<dim3(SS / 64, BB * NHH), 128, ASMEM>>>();

    cudaFuncSetAttribute(gemm_out_f16, cudaFuncAttributeMaxDynamicSharedMemorySize, QSMEM);
    gemm_out_f16<<<dim3(HH / 128, MM / 128), 256, QSMEM>>>(out);
}